// round 12
// baseline (speedup 1.0000x reference)
#include <cuda_runtime.h>
#include <cuda_bf16.h>
#include <math.h>
#include <stdint.h>

// ---------------- problem constants ----------------
#define Bc   2
#define Sc   1024
#define Dc   2048
#define HQc  16
#define HKVc 4
#define HDc  128
#define Ec   32
#define TOPK 4
#define Fc   1024
#define FSc  2048
#define Tc   (Bc * Sc)          // 2048 tokens
#define REPc (HQc / HKVc)       // 4
#define EPSc 1e-6f

// pipelined smem geometry (3 stages)
#define A_STRIDE 2560           // 128 rows x 20
#define B_STRIDE 2176           // 16 rows x 136
#define SMEM_NN  ((3 * A_STRIDE + 3 * B_STRIDE) * 4)   // 56832 B
#define SMEM_NT  ((3 * A_STRIDE + 3 * A_STRIDE) * 4)   // 61440 B

// ---------------- scratch (device globals; no allocations allowed) ----------------
__device__ float g_h[Tc * Dc];
__device__ float g_q[Tc * HQc * HDc];
__device__ float g_k[Tc * HKVc * HDc];
__device__ float g_v[Tc * HKVc * HDc];
__device__ float g_scores[(size_t)Bc * HQc * Sc * Sc];   // 134 MB
__device__ float g_attn[Tc * HQc * HDc];
__device__ float g_h2[Tc * Dc];
__device__ float g_x[Tc * Dc];
__device__ float g_g1[Tc * FSc];
__device__ float g_u1[Tc * FSc];
__device__ float g_eg[Tc * TOPK * Fc];
__device__ float g_eu[Tc * TOPK * Fc];
__device__ int   g_topi[Tc * TOPK];
__device__ float g_topw[Tc * TOPK];
__device__ int   g_counts[Ec];
__device__ int   g_offsets[Ec];
__device__ int   g_cursor[Ec];
__device__ int   g_slot_tok[Tc * TOPK];
__device__ float g_slot_w[Tc * TOPK];

// ---------------- tf32 helpers ----------------
__device__ __forceinline__ uint32_t f2tf(float x) {
    uint32_t r;
    asm("cvt.rna.tf32.f32 %0, %1;" : "=r"(r) : "f"(x));
    return r;
}
__device__ __forceinline__ void mma_tf32(float* c, const uint32_t* a, const uint32_t* b) {
    asm volatile(
        "mma.sync.aligned.m16n8k8.row.col.f32.tf32.tf32.f32 "
        "{%0,%1,%2,%3}, {%4,%5,%6,%7}, {%8,%9}, {%0,%1,%2,%3};"
        : "+f"(c[0]), "+f"(c[1]), "+f"(c[2]), "+f"(c[3])
        : "r"(a[0]), "r"(a[1]), "r"(a[2]), "r"(a[3]), "r"(b[0]), "r"(b[1]));
}

// ---------------- tiling decls shared by all pipelined GEMMs ----------------
#define TF_DECL                                                                 \
    int tid = threadIdx.x;                                                      \
    int lane = tid & 31, warp = tid >> 5;                                       \
    int grp = lane >> 2, tig = lane & 3;                                        \
    int wm = warp >> 1, wn = warp & 1;                                          \
    float acc[2][8][4] = {};                                                    \
    int aRow = tid >> 1, aCol = (tid & 1) * 8;                                  \
    int bRow = tid >> 4, bCol = (tid & 15) * 8;                                 \
    float4 ra0[2], ra1[2], rb0[2], rb1[2];

// store one staged tile (A: [128][20], B: [16][136]) with rna conversion
__device__ __forceinline__ void tfp_sts(uint32_t* Ab, uint32_t* Bb,
                                        int aRow, int aCol, int bRow, int bCol,
                                        float4 a0, float4 a1, float4 b0, float4 b1) {
    uint32_t* ap = Ab + aRow * 20 + aCol;
    ap[0] = f2tf(a0.x); ap[1] = f2tf(a0.y); ap[2] = f2tf(a0.z); ap[3] = f2tf(a0.w);
    ap[4] = f2tf(a1.x); ap[5] = f2tf(a1.y); ap[6] = f2tf(a1.z); ap[7] = f2tf(a1.w);
    uint32_t* bp = Bb + bRow * 136 + bCol;
    bp[0] = f2tf(b0.x); bp[1] = f2tf(b0.y); bp[2] = f2tf(b0.z); bp[3] = f2tf(b0.w);
    bp[4] = f2tf(b1.x); bp[5] = f2tf(b1.y); bp[6] = f2tf(b1.z); bp[7] = f2tf(b1.w);
}
// NT: both operands stored A-style [128][20]
__device__ __forceinline__ void tfp_sts_nt(uint32_t* Ab, uint32_t* Bb,
                                           int aRow, int aCol,
                                           float4 a0, float4 a1, float4 b0, float4 b1) {
    uint32_t* ap = Ab + aRow * 20 + aCol;
    ap[0] = f2tf(a0.x); ap[1] = f2tf(a0.y); ap[2] = f2tf(a0.z); ap[3] = f2tf(a0.w);
    ap[4] = f2tf(a1.x); ap[5] = f2tf(a1.y); ap[6] = f2tf(a1.z); ap[7] = f2tf(a1.w);
    uint32_t* bp = Bb + aRow * 20 + aCol;
    bp[0] = f2tf(b0.x); bp[1] = f2tf(b0.y); bp[2] = f2tf(b0.z); bp[3] = f2tf(b0.w);
    bp[4] = f2tf(b1.x); bp[5] = f2tf(b1.y); bp[6] = f2tf(b1.z); bp[7] = f2tf(b1.w);
}

__device__ __forceinline__ void tfp_compute(const uint32_t* Ab, const uint32_t* Bb,
                                            float acc[2][8][4],
                                            int grp, int tig, int wm, int wn) {
    #pragma unroll
    for (int ks = 0; ks < 2; ks++) {
        int kb = ks * 8;
        uint32_t af[2][4];
        #pragma unroll
        for (int mti = 0; mti < 2; mti++) {
            int r0 = wm * 32 + mti * 16 + grp;
            af[mti][0] = Ab[r0 * 20 + kb + tig];
            af[mti][1] = Ab[(r0 + 8) * 20 + kb + tig];
            af[mti][2] = Ab[r0 * 20 + kb + tig + 4];
            af[mti][3] = Ab[(r0 + 8) * 20 + kb + tig + 4];
        }
        #pragma unroll
        for (int nti = 0; nti < 8; nti++) {
            int nn = wn * 64 + nti * 8 + grp;
            uint32_t bf[2];
            bf[0] = Bb[(kb + tig) * 136 + nn];
            bf[1] = Bb[(kb + tig + 4) * 136 + nn];
            mma_tf32(acc[0][nti], af[0], bf);
            mma_tf32(acc[1][nti], af[1], bf);
        }
    }
}
__device__ __forceinline__ void tfp_compute_nt(const uint32_t* Ab, const uint32_t* Bb,
                                               float acc[2][8][4],
                                               int grp, int tig, int wm, int wn) {
    #pragma unroll
    for (int ks = 0; ks < 2; ks++) {
        int kb = ks * 8;
        uint32_t af[2][4];
        #pragma unroll
        for (int mti = 0; mti < 2; mti++) {
            int r0 = wm * 32 + mti * 16 + grp;
            af[mti][0] = Ab[r0 * 20 + kb + tig];
            af[mti][1] = Ab[(r0 + 8) * 20 + kb + tig];
            af[mti][2] = Ab[r0 * 20 + kb + tig + 4];
            af[mti][3] = Ab[(r0 + 8) * 20 + kb + tig + 4];
        }
        #pragma unroll
        for (int nti = 0; nti < 8; nti++) {
            int nn = wn * 64 + nti * 8 + grp;
            uint32_t bf[2];
            bf[0] = Bb[nn * 20 + kb + tig];
            bf[1] = Bb[nn * 20 + kb + tig + 4];
            mma_tf32(acc[0][nti], af[0], bf);
            mma_tf32(acc[1][nti], af[1], bf);
        }
    }
}

// distance-2 pipelined NN mainloop (A row-major [m][K], B row-major [k][N])
#define TFP_LDG_NN(s, k0)                                                        \
    { ra0[s] = *(const float4*)(Aptr + (k0));                                    \
      ra1[s] = *(const float4*)(Aptr + (k0) + 4);                                \
      rb0[s] = *(const float4*)(Bptr + (size_t)(k0) * ldbN);                     \
      rb1[s] = *(const float4*)(Bptr + (size_t)(k0) * ldbN + 4); }

#define TFP_MAINLOOP_NN(nTiles)                                                  \
    TFP_LDG_NN(0, 0); TFP_LDG_NN(1, 16);                                         \
    tfp_sts(Asm, Bsm, aRow, aCol, bRow, bCol, ra0[0], ra1[0], rb0[0], rb1[0]);   \
    __syncthreads();                                                             \
    for (int t = 0; t < (nTiles); t++) {                                         \
        if (t + 2 < (nTiles)) { int s_ = t & 1; TFP_LDG_NN(s_, (t + 2) << 4); }  \
        tfp_compute(Asm + (t % 3) * A_STRIDE, Bsm + (t % 3) * B_STRIDE,          \
                    acc, grp, tig, wm, wn);                                      \
        if (t + 1 < (nTiles)) {                                                  \
            int s_ = (t + 1) & 1;                                                \
            tfp_sts(Asm + ((t + 1) % 3) * A_STRIDE, Bsm + ((t + 1) % 3) * B_STRIDE, \
                    aRow, aCol, bRow, bCol, ra0[s_], ra1[s_], rb0[s_], rb1[s_]); \
        }                                                                        \
        __syncthreads();                                                         \
    }

// ---------------- RMSNorm over D ----------------
__global__ void __launch_bounds__(256) rmsnorm_kernel(const float* __restrict__ in,
                                                      const float* __restrict__ g,
                                                      float* __restrict__ out) {
    int t = blockIdx.x;
    const float* xi = in + (size_t)t * Dc;
    float* xo = out + (size_t)t * Dc;
    float s = 0.f;
    for (int i = threadIdx.x; i < Dc; i += 256) { float v = xi[i]; s += v * v; }
    __shared__ float red[256];
    red[threadIdx.x] = s; __syncthreads();
    for (int st = 128; st > 0; st >>= 1) {
        if (threadIdx.x < st) red[threadIdx.x] += red[threadIdx.x + st];
        __syncthreads();
    }
    float inv = rsqrtf(red[0] / (float)Dc + EPSc);
    for (int i = threadIdx.x; i < Dc; i += 256) xo[i] = xi[i] * inv * g[i];
}

// ---------------- per-head RMSNorm + neox RoPE (in place) ----------------
__global__ void __launch_bounds__(128) qknorm_rope_kernel(float* __restrict__ buf,
                                                          const float* __restrict__ nrm,
                                                          const int* __restrict__ positions,
                                                          int H) {
    int t = blockIdx.x, h = blockIdx.y, d = threadIdx.x;
    float* p = buf + ((size_t)t * H + h) * HDc;
    float v = p[d];
    float ss = v * v;
    for (int o = 16; o > 0; o >>= 1) ss += __shfl_down_sync(0xffffffffu, ss, o);
    __shared__ float wred[4];
    if ((d & 31) == 0) wred[d >> 5] = ss;
    __syncthreads();
    float sum = wred[0] + wred[1] + wred[2] + wred[3];
    float inv = rsqrtf(sum / (float)HDc + EPSc);
    __shared__ float sv[HDc];
    sv[d] = v * inv * nrm[d];
    __syncthreads();
    float fpos = (float)positions[t];
    int i = (d < 64) ? d : d - 64;
    float freq = expf(-(float)i * (13.815510557964274f / 64.0f)); // ln(1e6)/64
    float ang = fpos * freq;
    float sn, cs; sincosf(ang, &sn, &cs);
    float x1 = (d < 64) ? sv[d] : sv[d - 64];
    float x2 = (d < 64) ? sv[d + 64] : sv[d];
    p[d] = (d < 64) ? (x1 * cs - x2 * sn) : (x1 * sn + x2 * cs);
}

// ---------------- fused QKV projection (tf32, pipelined) ----------------
__global__ void __launch_bounds__(256, 2) qkv_tf32_kernel(const float* __restrict__ A,
                                                          const float* __restrict__ wq,
                                                          const float* __restrict__ wk,
                                                          const float* __restrict__ wv,
                                                          float* __restrict__ oq,
                                                          float* __restrict__ ok,
                                                          float* __restrict__ ov) {
    extern __shared__ uint32_t dsm[];
    uint32_t* Asm = dsm;
    uint32_t* Bsm = dsm + 3 * A_STRIDE;
    int nb = blockIdx.x;
    const float* Bsel; float* outp; int ldbN; int nloc;
    if (nb < 16)      { Bsel = wq; outp = oq; ldbN = HQc * HDc;  nloc = nb; }
    else if (nb < 20) { Bsel = wk; outp = ok; ldbN = HKVc * HDc; nloc = nb - 16; }
    else              { Bsel = wv; outp = ov; ldbN = HKVc * HDc; nloc = nb - 20; }
    int n0 = nloc * 128;
    int m0 = blockIdx.y * 128;
    TF_DECL;
    const float* Aptr = A + (size_t)(m0 + aRow) * Dc + aCol;
    const float* Bptr = Bsel + (size_t)bRow * ldbN + n0 + bCol;

    TFP_MAINLOOP_NN(Dc / 16);

    #pragma unroll
    for (int mti = 0; mti < 2; mti++)
        #pragma unroll
        for (int nti = 0; nti < 8; nti++) {
            int m = m0 + wm * 32 + mti * 16 + grp;
            int n = n0 + wn * 64 + nti * 8 + tig * 2;
            const float* cc = acc[mti][nti];
            outp[(size_t)m * ldbN + n]           = cc[0];
            outp[(size_t)m * ldbN + n + 1]       = cc[1];
            outp[(size_t)(m + 8) * ldbN + n]     = cc[2];
            outp[(size_t)(m + 8) * ldbN + n + 1] = cc[3];
        }
}

// ---------------- generic tf32 GEMM (pipelined): C = A@B (+addC) ----------------
__global__ void __launch_bounds__(256, 2) gemm_tf32_kernel(const float* __restrict__ A,
                                                           const float* __restrict__ B,
                                                           float* __restrict__ C,
                                                           const float* __restrict__ addC,
                                                           int K, int lda, int ldbN, int ldc) {
    extern __shared__ uint32_t dsm[];
    uint32_t* Asm = dsm;
    uint32_t* Bsm = dsm + 3 * A_STRIDE;
    int m0 = blockIdx.y * 128;
    int n0 = blockIdx.x * 128;
    TF_DECL;
    const float* Aptr = A + (size_t)(m0 + aRow) * lda + aCol;
    const float* Bptr = B + (size_t)bRow * ldbN + n0 + bCol;

    TFP_MAINLOOP_NN(K / 16);

    #pragma unroll
    for (int mti = 0; mti < 2; mti++)
        #pragma unroll
        for (int nti = 0; nti < 8; nti++) {
            int m = m0 + wm * 32 + mti * 16 + grp;
            int n = n0 + wn * 64 + nti * 8 + tig * 2;
            const float* cc = acc[mti][nti];
            float v0 = cc[0], v1 = cc[1], v2 = cc[2], v3 = cc[3];
            if (addC) {
                v0 += addC[(size_t)m * ldc + n];
                v1 += addC[(size_t)m * ldc + n + 1];
                v2 += addC[(size_t)(m + 8) * ldc + n];
                v3 += addC[(size_t)(m + 8) * ldc + n + 1];
            }
            C[(size_t)m * ldc + n]           = v0;
            C[(size_t)m * ldc + n + 1]       = v1;
            C[(size_t)(m + 8) * ldc + n]     = v2;
            C[(size_t)(m + 8) * ldc + n + 1] = v3;
        }
}

// ---------------- QK^T scores (tf32 NT, pipelined, causal tile skip) ----------------
__global__ void __launch_bounds__(256, 2) qk_tf32_kernel(const float* __restrict__ q,
                                                         const float* __restrict__ k,
                                                         float* __restrict__ scores) {
    extern __shared__ uint32_t dsm[];
    uint32_t* Asm = dsm;
    uint32_t* Bsm = dsm + 3 * A_STRIDE;
    int kb0 = blockIdx.x * 128, q0 = blockIdx.y * 128, z = blockIdx.z;
    if (kb0 > q0) return;
    int b = z / HQc, h = z % HQc, kvh = h / REPc;
    TF_DECL;
    (void)bRow; (void)bCol;
    const float* Aptr = q + ((size_t)(b * Sc + q0 + aRow) * HQc + h) * HDc + aCol;
    const float* Bptr = k + ((size_t)(b * Sc + kb0 + aRow) * HKVc + kvh) * HDc + aCol;

    // prologue + loop (NT: B loaded row-wise like A)
    #define TFP_LDG_NT(s, k0)                                                    \
        { ra0[s] = *(const float4*)(Aptr + (k0));                                \
          ra1[s] = *(const float4*)(Aptr + (k0) + 4);                            \
          rb0[s] = *(const float4*)(Bptr + (k0));                                \
          rb1[s] = *(const float4*)(Bptr + (k0) + 4); }
    const int nTiles = HDc / 16;   // 8
    TFP_LDG_NT(0, 0); TFP_LDG_NT(1, 16);
    tfp_sts_nt(Asm, Bsm, aRow, aCol, ra0[0], ra1[0], rb0[0], rb1[0]);
    __syncthreads();
    for (int t = 0; t < nTiles; t++) {
        if (t + 2 < nTiles) { int s_ = t & 1; TFP_LDG_NT(s_, (t + 2) << 4); }
        tfp_compute_nt(Asm + (t % 3) * A_STRIDE, Bsm + (t % 3) * A_STRIDE,
                       acc, grp, tig, wm, wn);
        if (t + 1 < nTiles) {
            int s_ = (t + 1) & 1;
            tfp_sts_nt(Asm + ((t + 1) % 3) * A_STRIDE, Bsm + ((t + 1) % 3) * A_STRIDE,
                       aRow, aCol, ra0[s_], ra1[s_], rb0[s_], rb1[s_]);
        }
        __syncthreads();
    }
    #undef TFP_LDG_NT

    const float scale = 0.08838834764831845f; // 128^-0.5
    #pragma unroll
    for (int mti = 0; mti < 2; mti++)
        #pragma unroll
        for (int nti = 0; nti < 8; nti++) {
            int m = q0 + wm * 32 + mti * 16 + grp;
            int n = kb0 + wn * 64 + nti * 8 + tig * 2;
            const float* cc = acc[mti][nti];
            float* row0 = scores + ((size_t)z * Sc + m) * Sc;
            float* row8 = scores + ((size_t)z * Sc + m + 8) * Sc;
            row0[n]     = cc[0] * scale;
            row0[n + 1] = cc[1] * scale;
            row8[n]     = cc[2] * scale;
            row8[n + 1] = cc[3] * scale;
        }
}

// ---------------- causal softmax: normalize [0..qi], zero-fill only the attnv band ----------------
__global__ void __launch_bounds__(256) softmax_kernel(float* __restrict__ scores) {
    int qi = blockIdx.x, z = blockIdx.y;
    float* row = scores + ((size_t)z * Sc + qi) * Sc;
    int n = qi + 1;
    int tid = threadIdx.x;
    __shared__ float red[256];
    float m = -1e30f;
    for (int i = tid; i < n; i += 256) m = fmaxf(m, row[i]);
    red[tid] = m; __syncthreads();
    for (int st = 128; st > 0; st >>= 1) {
        if (tid < st) red[tid] = fmaxf(red[tid], red[tid + st]);
        __syncthreads();
    }
    float mx = red[0]; __syncthreads();
    float s = 0.f;
    for (int i = tid; i < n; i += 256) s += expf(row[i] - mx);
    red[tid] = s; __syncthreads();
    for (int st = 128; st > 0; st >>= 1) {
        if (tid < st) red[tid] += red[tid + st];
        __syncthreads();
    }
    float inv = 1.f / red[0];
    for (int i = tid; i < n; i += 256) row[i] = expf(row[i] - mx) * inv;
    int bandEnd = (qi & ~127) + 128;   // attnv reads k in [0, bandEnd)
    for (int i = n + tid; i < bandEnd; i += 256) row[i] = 0.f;
}

// ---------------- attn = P @ V (tf32, pipelined, causal K truncation) ----------------
__global__ void __launch_bounds__(256, 2) attnv_tf32_kernel(const float* __restrict__ P,
                                                            const float* __restrict__ v,
                                                            float* __restrict__ attn) {
    extern __shared__ uint32_t dsm[];
    uint32_t* Asm = dsm;
    uint32_t* Bsm = dsm + 3 * A_STRIDE;
    int z = blockIdx.z;
    int b = z / HQc, h = z % HQc, kvh = h / REPc;
    int m0 = blockIdx.y * 128;
    const int ldbN = HKVc * HDc;
    TF_DECL;
    const float* Aptr = P + (size_t)z * Sc * Sc + (size_t)(m0 + aRow) * Sc + aCol;
    const float* Bptr = v + ((size_t)b * Sc * HKVc + kvh) * HDc + (size_t)bRow * ldbN + bCol;

    int nT = (m0 + 128) >> 4;
    TFP_MAINLOOP_NN(nT);

    #pragma unroll
    for (int mti = 0; mti < 2; mti++)
        #pragma unroll
        for (int nti = 0; nti < 8; nti++) {
            int m = m0 + wm * 32 + mti * 16 + grp;
            int n = wn * 64 + nti * 8 + tig * 2;
            const float* cc = acc[mti][nti];
            attn[((size_t)(b * Sc + m) * HQc + h) * HDc + n]         = cc[0];
            attn[((size_t)(b * Sc + m) * HQc + h) * HDc + n + 1]     = cc[1];
            attn[((size_t)(b * Sc + m + 8) * HQc + h) * HDc + n]     = cc[2];
            attn[((size_t)(b * Sc + m + 8) * HQc + h) * HDc + n + 1] = cc[3];
        }
}

// ---------------- elementwise silu(a)*b -> a ----------------
__global__ void __launch_bounds__(256) silumul_kernel(float* __restrict__ a,
                                                      const float* __restrict__ b,
                                                      int n) {
    int i = blockIdx.x * 256 + threadIdx.x;
    if (i < n) {
        float v = a[i];
        a[i] = v / (1.f + expf(-v)) * b[i];
    }
}

// ---------------- router: logits, sigmoid, top-4, renorm ----------------
__global__ void __launch_bounds__(256) router_kernel(const float* __restrict__ x,
                                                     const float* __restrict__ gate_w) {
    int t = blockIdx.x;
    int tid = threadIdx.x;
    int lane = tid & 31, w = tid >> 5;
    const float* xr = x + (size_t)t * Dc;
    float acc[4] = {0.f, 0.f, 0.f, 0.f};
    for (int d = lane; d < Dc; d += 32) {
        float xv = xr[d];
        #pragma unroll
        for (int j = 0; j < 4; j++)
            acc[j] = fmaf(xv, gate_w[(size_t)d * Ec + w * 4 + j], acc[j]);
    }
    #pragma unroll
    for (int j = 0; j < 4; j++)
        for (int o = 16; o > 0; o >>= 1)
            acc[j] += __shfl_down_sync(0xffffffffu, acc[j], o);
    __shared__ float lg[Ec];
    if (lane == 0) {
        #pragma unroll
        for (int j = 0; j < 4; j++) lg[w * 4 + j] = acc[j];
    }
    __syncthreads();
    if (tid == 0) {
        float gg[Ec];
        #pragma unroll
        for (int e = 0; e < Ec; e++) gg[e] = 1.f / (1.f + expf(-lg[e]));
        float tv[TOPK]; int ti[TOPK]; float sum = 0.f;
        for (int j = 0; j < TOPK; j++) {
            int best = 0; float bv = -1e30f;
            for (int e = 0; e < Ec; e++)
                if (gg[e] > bv) { bv = gg[e]; best = e; }
            gg[best] = -1e30f;
            tv[j] = bv; ti[j] = best; sum += bv;
        }
        float inv = 1.f / sum;
        for (int j = 0; j < TOPK; j++) {
            g_topi[t * TOPK + j] = ti[j];
            g_topw[t * TOPK + j] = tv[j] * inv;
        }
    }
}

// ---------------- expert grouping ----------------
__global__ void __launch_bounds__(256) count_scan_kernel() {
    __shared__ int sc[Ec];
    int tid = threadIdx.x;
    if (tid < Ec) sc[tid] = 0;
    __syncthreads();
    for (int i = tid; i < Tc * TOPK; i += 256) atomicAdd(&sc[g_topi[i]], 1);
    __syncthreads();
    if (tid == 0) {
        int run = 0;
        for (int e = 0; e < Ec; e++) {
            g_offsets[e] = run; g_cursor[e] = run; g_counts[e] = sc[e];
            run += sc[e];
        }
    }
}

__global__ void __launch_bounds__(256) scatter_kernel() {
    int i = blockIdx.x * 256 + threadIdx.x;
    if (i < Tc * TOPK) {
        int t = i >> 2;
        int e = g_topi[i];
        int p = atomicAdd(&g_cursor[e], 1);
        g_slot_tok[p] = t;
        g_slot_w[p] = g_topw[i];
    }
}

// ---------------- routed expert up/gate GEMM (tf32, pipelined, gathered A rows) ----------------
__global__ void __launch_bounds__(256, 2) moe_up_tf32_kernel(const float* __restrict__ X,
                                                             const float* __restrict__ W,
                                                             float* __restrict__ Cb,
                                                             int Nn, int Kd) {
    extern __shared__ uint32_t dsm[];
    uint32_t* Asm = dsm;
    uint32_t* Bsm = dsm + 3 * A_STRIDE;
    int e = blockIdx.z;
    int cnt = g_counts[e];
    int m0 = blockIdx.y * 128;
    if (m0 >= cnt) return;
    int off = g_offsets[e];
    int n0 = blockIdx.x * 128;
    const int ldbN = Nn;
    TF_DECL;
    int gRow = m0 + aRow;
    int srow = (gRow < cnt) ? g_slot_tok[off + gRow] : g_slot_tok[off];
    const float* Aptr = X + (size_t)srow * Kd + aCol;
    const float* Bptr = W + (size_t)e * Kd * Nn + (size_t)bRow * Nn + n0 + bCol;

    int nT = Kd / 16;
    TFP_MAINLOOP_NN(nT);

    #pragma unroll
    for (int mti = 0; mti < 2; mti++)
        #pragma unroll
        for (int nti = 0; nti < 8; nti++) {
            int r = m0 + wm * 32 + mti * 16 + grp;
            int n = n0 + wn * 64 + nti * 8 + tig * 2;
            const float* cc = acc[mti][nti];
            if (r < cnt) {
                Cb[(size_t)(off + r) * Nn + n]     = cc[0];
                Cb[(size_t)(off + r) * Nn + n + 1] = cc[1];
            }
            if (r + 8 < cnt) {
                Cb[(size_t)(off + r + 8) * Nn + n]     = cc[2];
                Cb[(size_t)(off + r + 8) * Nn + n + 1] = cc[3];
            }
        }
}

// ---------------- routed expert down GEMM (tf32, pipelined): atomicAdd into out ----------------
__global__ void __launch_bounds__(256, 2) moe_down_tf32_kernel(const float* __restrict__ Ibuf,
                                                               const float* __restrict__ Wd,
                                                               float* __restrict__ out,
                                                               int Nn, int Kd) {
    extern __shared__ uint32_t dsm[];
    uint32_t* Asm = dsm;
    uint32_t* Bsm = dsm + 3 * A_STRIDE;
    int e = blockIdx.z;
    int cnt = g_counts[e];
    int m0 = blockIdx.y * 128;
    if (m0 >= cnt) return;
    int off = g_offsets[e];
    int n0 = blockIdx.x * 128;
    const int ldbN = Nn;
    TF_DECL;
    int gRow = m0 + aRow;
    int arow = off + ((gRow < cnt) ? gRow : 0);
    const float* Aptr = Ibuf + (size_t)arow * Kd + aCol;
    const float* Bptr = Wd + (size_t)e * Kd * Nn + (size_t)bRow * Nn + n0 + bCol;

    int nT = Kd / 16;
    TFP_MAINLOOP_NN(nT);

    #pragma unroll
    for (int mti = 0; mti < 2; mti++)
        #pragma unroll
        for (int nti = 0; nti < 8; nti++) {
            int r = m0 + wm * 32 + mti * 16 + grp;
            int n = n0 + wn * 64 + nti * 8 + tig * 2;
            const float* cc = acc[mti][nti];
            if (r < cnt) {
                int slot = off + r;
                float wgt = g_slot_w[slot];
                int tok = g_slot_tok[slot];
                atomicAdd(&out[(size_t)tok * Nn + n],     wgt * cc[0]);
                atomicAdd(&out[(size_t)tok * Nn + n + 1], wgt * cc[1]);
            }
            if (r + 8 < cnt) {
                int slot = off + r + 8;
                float wgt = g_slot_w[slot];
                int tok = g_slot_tok[slot];
                atomicAdd(&out[(size_t)tok * Nn + n],     wgt * cc[2]);
                atomicAdd(&out[(size_t)tok * Nn + n + 1], wgt * cc[3]);
            }
        }
}

// ---------------- host launch ----------------
extern "C" void kernel_launch(void* const* d_in, const int* in_sizes, int n_in,
                              void* d_out, int out_size) {
    const int*   positions = (const int*)d_in[0];
    const float* hidden    = (const float*)d_in[1];
    const float* in_ln     = (const float*)d_in[2];
    const float* post_ln   = (const float*)d_in[3];
    const float* q_norm    = (const float*)d_in[4];
    const float* k_norm    = (const float*)d_in[5];
    const float* wq        = (const float*)d_in[6];
    const float* wk        = (const float*)d_in[7];
    const float* wv        = (const float*)d_in[8];
    const float* wo        = (const float*)d_in[9];
    const float* gate_w    = (const float*)d_in[10];
    const float* sh_wg     = (const float*)d_in[11];
    const float* sh_wu     = (const float*)d_in[12];
    const float* sh_wd     = (const float*)d_in[13];
    const float* e_wg      = (const float*)d_in[14];
    const float* e_wu      = (const float*)d_in[15];
    const float* e_wd      = (const float*)d_in[16];
    float* out = (float*)d_out;

    float *p_h, *p_q, *p_k, *p_v, *p_scores, *p_attn, *p_h2, *p_x, *p_g1, *p_u1,
          *p_eg, *p_eu;
    cudaGetSymbolAddress((void**)&p_h, g_h);
    cudaGetSymbolAddress((void**)&p_q, g_q);
    cudaGetSymbolAddress((void**)&p_k, g_k);
    cudaGetSymbolAddress((void**)&p_v, g_v);
    cudaGetSymbolAddress((void**)&p_scores, g_scores);
    cudaGetSymbolAddress((void**)&p_attn, g_attn);
    cudaGetSymbolAddress((void**)&p_h2, g_h2);
    cudaGetSymbolAddress((void**)&p_x, g_x);
    cudaGetSymbolAddress((void**)&p_g1, g_g1);
    cudaGetSymbolAddress((void**)&p_u1, g_u1);
    cudaGetSymbolAddress((void**)&p_eg, g_eg);
    cudaGetSymbolAddress((void**)&p_eu, g_eu);

    cudaFuncSetAttribute(qkv_tf32_kernel,      cudaFuncAttributeMaxDynamicSharedMemorySize, SMEM_NN);
    cudaFuncSetAttribute(gemm_tf32_kernel,     cudaFuncAttributeMaxDynamicSharedMemorySize, SMEM_NN);
    cudaFuncSetAttribute(qk_tf32_kernel,       cudaFuncAttributeMaxDynamicSharedMemorySize, SMEM_NT);
    cudaFuncSetAttribute(attnv_tf32_kernel,    cudaFuncAttributeMaxDynamicSharedMemorySize, SMEM_NN);
    cudaFuncSetAttribute(moe_up_tf32_kernel,   cudaFuncAttributeMaxDynamicSharedMemorySize, SMEM_NN);
    cudaFuncSetAttribute(moe_down_tf32_kernel, cudaFuncAttributeMaxDynamicSharedMemorySize, SMEM_NN);

    // 1. input RMSNorm
    rmsnorm_kernel<<<Tc, 256>>>(hidden, in_ln, p_h);

    // 2. fused QKV projection
    qkv_tf32_kernel<<<dim3(24, Tc / 128), 256, SMEM_NN>>>(p_h, wq, wk, wv, p_q, p_k, p_v);

    // 3. qk-norm + RoPE
    qknorm_rope_kernel<<<dim3(Tc, HQc), 128>>>(p_q, q_norm, positions, HQc);
    qknorm_rope_kernel<<<dim3(Tc, HKVc), 128>>>(p_k, k_norm, positions, HKVc);

    // 4. scores (tf32 NT, causal tile skip)
    qk_tf32_kernel<<<dim3(Sc / 128, Sc / 128, Bc * HQc), 256, SMEM_NT>>>(p_q, p_k, p_scores);

    // 5. causal softmax (bounded zero-fill)
    softmax_kernel<<<dim3(Sc, Bc * HQc), 256>>>(p_scores);

    // 6. attn = P @ V
    attnv_tf32_kernel<<<dim3(1, Sc / 128, Bc * HQc), 256, SMEM_NN>>>(p_scores, p_v, p_attn);

    // 7. output proj + residual
    gemm_tf32_kernel<<<dim3(Dc / 128, Tc / 128), 256, SMEM_NN>>>(p_attn, wo, p_h2, hidden,
        HQc * HDc, HQc * HDc, Dc, Dc);

    // 8. post-attn RMSNorm
    rmsnorm_kernel<<<Tc, 256>>>(p_h2, post_ln, p_x);

    // 9. shared expert SwiGLU; down-proj fused with resid2 directly into out
    gemm_tf32_kernel<<<dim3(FSc / 128, Tc / 128), 256, SMEM_NN>>>(p_x, sh_wg, p_g1, nullptr,
        Dc, Dc, FSc, FSc);
    gemm_tf32_kernel<<<dim3(FSc / 128, Tc / 128), 256, SMEM_NN>>>(p_x, sh_wu, p_u1, nullptr,
        Dc, Dc, FSc, FSc);
    silumul_kernel<<<(Tc * FSc + 255) / 256, 256>>>(p_g1, p_u1, Tc * FSc);
    // out = shared + resid2 (replaces old g_sh + combine_kernel); moe atomics add on top
    gemm_tf32_kernel<<<dim3(Dc / 128, Tc / 128), 256, SMEM_NN>>>(p_g1, sh_wd, out, p_h2,
        FSc, FSc, Dc, Dc);

    // 10. routing + grouping
    router_kernel<<<Tc, 256>>>(p_x, gate_w);
    count_scan_kernel<<<1, 256>>>();
    scatter_kernel<<<(Tc * TOPK + 255) / 256, 256>>>();

    // 11. routed experts: gate/up (gathered), silu-mul
    moe_up_tf32_kernel<<<dim3(Fc / 128, (Tc * TOPK) / 128, Ec), 256, SMEM_NN>>>(p_x, e_wg, p_eg, Fc, Dc);
    moe_up_tf32_kernel<<<dim3(Fc / 128, (Tc * TOPK) / 128, Ec), 256, SMEM_NN>>>(p_x, e_wu, p_eu, Fc, Dc);
    silumul_kernel<<<(Tc * TOPK * Fc + 255) / 256, 256>>>(p_eg, p_eu, Tc * TOPK * Fc);

    // 12. routed down-proj, weighted atomic accumulate into out
    moe_down_tf32_kernel<<<dim3(Dc / 128, (Tc * TOPK) / 128, Ec), 256, SMEM_NN>>>(p_eg, e_wd, out, Dc, Fc);
}

// round 14
// speedup vs baseline: 1.2896x; 1.2896x over previous
#include <cuda_runtime.h>
#include <cuda_bf16.h>
#include <math.h>
#include <stdint.h>

// ---------------- problem constants ----------------
#define Bc   2
#define Sc   1024
#define Dc   2048
#define HQc  16
#define HKVc 4
#define HDc  128
#define Ec   32
#define TOPK 4
#define Fc   1024
#define FSc  2048
#define Tc   (Bc * Sc)          // 2048 tokens
#define REPc (HQc / HKVc)       // 4
#define EPSc 1e-6f

// ---------------- scratch (device globals; no allocations allowed) ----------------
__device__ float g_h[Tc * Dc];
__device__ float g_q[Tc * HQc * HDc];
__device__ float g_k[Tc * HKVc * HDc];
__device__ float g_v[Tc * HKVc * HDc];
__device__ float g_scores[(size_t)Bc * HQc * Sc * Sc];   // 134 MB
__device__ float g_attn[Tc * HQc * HDc];
__device__ float g_h2[Tc * Dc];
__device__ float g_x[Tc * Dc];
__device__ float g_g1[Tc * FSc];
__device__ float g_u1[Tc * FSc];
__device__ float g_eg[Tc * TOPK * Fc];
__device__ float g_eu[Tc * TOPK * Fc];
__device__ int   g_topi[Tc * TOPK];
__device__ float g_topw[Tc * TOPK];
__device__ int   g_counts[Ec];
__device__ int   g_offsets[Ec];
__device__ int   g_cursor[Ec];
__device__ int   g_slot_tok[Tc * TOPK];
__device__ float g_slot_w[Tc * TOPK];

// ---------------- tf32 helpers ----------------
__device__ __forceinline__ uint32_t f2tf(float x) {
    uint32_t r;
    asm("cvt.rna.tf32.f32 %0, %1;" : "=r"(r) : "f"(x));
    return r;
}
__device__ __forceinline__ void mma_tf32(float* c, const uint32_t* a, const uint32_t* b) {
    asm volatile(
        "mma.sync.aligned.m16n8k8.row.col.f32.tf32.tf32.f32 "
        "{%0,%1,%2,%3}, {%4,%5,%6,%7}, {%8,%9}, {%0,%1,%2,%3};"
        : "+f"(c[0]), "+f"(c[1]), "+f"(c[2]), "+f"(c[3])
        : "r"(a[0]), "r"(a[1]), "r"(a[2]), "r"(a[3]), "r"(b[0]), "r"(b[1]));
}

// ---------- tf32 GEMM shared fragments (R4 measured-good double-buffer) ----------
#define TF_DECL                                                                 \
    int tid = threadIdx.x;                                                      \
    int lane = tid & 31, warp = tid >> 5;                                       \
    int grp = lane >> 2, tig = lane & 3;                                        \
    int wm = warp >> 1, wn = warp & 1;                                          \
    float acc[2][8][4];                                                         \
    _Pragma("unroll")                                                           \
    for (int i_ = 0; i_ < 2; i_++)                                              \
        _Pragma("unroll")                                                       \
        for (int j_ = 0; j_ < 8; j_++)                                          \
            _Pragma("unroll")                                                   \
            for (int q_ = 0; q_ < 4; q_++) acc[i_][j_][q_] = 0.f;               \
    int aRow = tid >> 1, aCol = (tid & 1) * 8;                                  \
    int bRow = tid >> 4, bCol = (tid & 15) * 8;

#define TF_STORE(buf) {                                                         \
    uint32_t* ap_ = &As[buf][aRow][aCol];                                       \
    ap_[0] = f2tf(av0.x); ap_[1] = f2tf(av0.y);                                 \
    ap_[2] = f2tf(av0.z); ap_[3] = f2tf(av0.w);                                 \
    ap_[4] = f2tf(av1.x); ap_[5] = f2tf(av1.y);                                 \
    ap_[6] = f2tf(av1.z); ap_[7] = f2tf(av1.w);                                 \
    uint32_t* bp_ = &Bs[buf][bRow][bCol];                                       \
    bp_[0] = f2tf(bv0.x); bp_[1] = f2tf(bv0.y);                                 \
    bp_[2] = f2tf(bv0.z); bp_[3] = f2tf(bv0.w);                                 \
    bp_[4] = f2tf(bv1.x); bp_[5] = f2tf(bv1.y);                                 \
    bp_[6] = f2tf(bv1.z); bp_[7] = f2tf(bv1.w); }

#define TF_COMPUTE(buf)                                                         \
    _Pragma("unroll")                                                           \
    for (int ks_ = 0; ks_ < 2; ks_++) {                                         \
        int kb_ = ks_ * 8;                                                      \
        uint32_t af_[2][4];                                                     \
        _Pragma("unroll")                                                       \
        for (int mti_ = 0; mti_ < 2; mti_++) {                                  \
            int r0_ = wm * 32 + mti_ * 16 + grp;                                \
            af_[mti_][0] = As[buf][r0_][kb_ + tig];                             \
            af_[mti_][1] = As[buf][r0_ + 8][kb_ + tig];                         \
            af_[mti_][2] = As[buf][r0_][kb_ + tig + 4];                         \
            af_[mti_][3] = As[buf][r0_ + 8][kb_ + tig + 4];                     \
        }                                                                       \
        _Pragma("unroll")                                                       \
        for (int nti_ = 0; nti_ < 8; nti_++) {                                  \
            uint32_t bf_[2];                                                    \
            int nn_ = wn * 64 + nti_ * 8 + grp;                                 \
            bf_[0] = Bs[buf][kb_ + tig][nn_];                                   \
            bf_[1] = Bs[buf][kb_ + tig + 4][nn_];                               \
            mma_tf32(acc[0][nti_], af_[0], bf_);                                \
            mma_tf32(acc[1][nti_], af_[1], bf_);                                \
        }                                                                       \
    }

// NT variants: B stored A-style [128][20]
#define TF_STORE_NT(buf) {                                                      \
    uint32_t* ap_ = &As[buf][aRow][aCol];                                       \
    ap_[0] = f2tf(av0.x); ap_[1] = f2tf(av0.y);                                 \
    ap_[2] = f2tf(av0.z); ap_[3] = f2tf(av0.w);                                 \
    ap_[4] = f2tf(av1.x); ap_[5] = f2tf(av1.y);                                 \
    ap_[6] = f2tf(av1.z); ap_[7] = f2tf(av1.w);                                 \
    uint32_t* bp_ = &Bs2[buf][aRow][aCol];                                      \
    bp_[0] = f2tf(bv0.x); bp_[1] = f2tf(bv0.y);                                 \
    bp_[2] = f2tf(bv0.z); bp_[3] = f2tf(bv0.w);                                 \
    bp_[4] = f2tf(bv1.x); bp_[5] = f2tf(bv1.y);                                 \
    bp_[6] = f2tf(bv1.z); bp_[7] = f2tf(bv1.w); }

#define TF_COMPUTE_NT(buf)                                                      \
    _Pragma("unroll")                                                           \
    for (int ks_ = 0; ks_ < 2; ks_++) {                                         \
        int kb_ = ks_ * 8;                                                      \
        uint32_t af_[2][4];                                                     \
        _Pragma("unroll")                                                       \
        for (int mti_ = 0; mti_ < 2; mti_++) {                                  \
            int r0_ = wm * 32 + mti_ * 16 + grp;                                \
            af_[mti_][0] = As[buf][r0_][kb_ + tig];                             \
            af_[mti_][1] = As[buf][r0_ + 8][kb_ + tig];                         \
            af_[mti_][2] = As[buf][r0_][kb_ + tig + 4];                         \
            af_[mti_][3] = As[buf][r0_ + 8][kb_ + tig + 4];                     \
        }                                                                       \
        _Pragma("unroll")                                                       \
        for (int nti_ = 0; nti_ < 8; nti_++) {                                  \
            uint32_t bf_[2];                                                    \
            int nn_ = wn * 64 + nti_ * 8 + grp;                                 \
            bf_[0] = Bs2[buf][nn_][kb_ + tig];                                  \
            bf_[1] = Bs2[buf][nn_][kb_ + tig + 4];                              \
            mma_tf32(acc[0][nti_], af_[0], bf_);                                \
            mma_tf32(acc[1][nti_], af_[1], bf_);                                \
        }                                                                       \
    }

// ---------------- RMSNorm over D ----------------
__global__ void __launch_bounds__(256) rmsnorm_kernel(const float* __restrict__ in,
                                                      const float* __restrict__ g,
                                                      float* __restrict__ out) {
    int t = blockIdx.x;
    const float* xi = in + (size_t)t * Dc;
    float* xo = out + (size_t)t * Dc;
    float s = 0.f;
    for (int i = threadIdx.x; i < Dc; i += 256) { float v = xi[i]; s += v * v; }
    __shared__ float red[256];
    red[threadIdx.x] = s; __syncthreads();
    for (int st = 128; st > 0; st >>= 1) {
        if (threadIdx.x < st) red[threadIdx.x] += red[threadIdx.x + st];
        __syncthreads();
    }
    float inv = rsqrtf(red[0] / (float)Dc + EPSc);
    for (int i = threadIdx.x; i < Dc; i += 256) xo[i] = xi[i] * inv * g[i];
}

// ---------------- per-head RMSNorm + neox RoPE (in place) ----------------
__global__ void __launch_bounds__(128) qknorm_rope_kernel(float* __restrict__ buf,
                                                          const float* __restrict__ nrm,
                                                          const int* __restrict__ positions,
                                                          int H) {
    int t = blockIdx.x, h = blockIdx.y, d = threadIdx.x;
    float* p = buf + ((size_t)t * H + h) * HDc;
    float v = p[d];
    float ss = v * v;
    for (int o = 16; o > 0; o >>= 1) ss += __shfl_down_sync(0xffffffffu, ss, o);
    __shared__ float wred[4];
    if ((d & 31) == 0) wred[d >> 5] = ss;
    __syncthreads();
    float sum = wred[0] + wred[1] + wred[2] + wred[3];
    float inv = rsqrtf(sum / (float)HDc + EPSc);
    __shared__ float sv[HDc];
    sv[d] = v * inv * nrm[d];
    __syncthreads();
    float fpos = (float)positions[t];
    int i = (d < 64) ? d : d - 64;
    float freq = expf(-(float)i * (13.815510557964274f / 64.0f)); // ln(1e6)/64
    float ang = fpos * freq;
    float sn, cs; sincosf(ang, &sn, &cs);
    float x1 = (d < 64) ? sv[d] : sv[d - 64];
    float x2 = (d < 64) ? sv[d + 64] : sv[d];
    p[d] = (d < 64) ? (x1 * cs - x2 * sn) : (x1 * sn + x2 * cs);
}

// ---------------- fused QKV projection (tf32, R4 double-buffer) ----------------
__global__ void __launch_bounds__(256) qkv_tf32_kernel(const float* __restrict__ A,
                                                       const float* __restrict__ wq,
                                                       const float* __restrict__ wk,
                                                       const float* __restrict__ wv,
                                                       float* __restrict__ oq,
                                                       float* __restrict__ ok,
                                                       float* __restrict__ ov) {
    __shared__ uint32_t As[2][128][20];
    __shared__ uint32_t Bs[2][16][136];
    int nb = blockIdx.x;
    const float* Bsel; float* outp; int ldbN; int nloc;
    if (nb < 16)      { Bsel = wq; outp = oq; ldbN = HQc * HDc;  nloc = nb; }
    else if (nb < 20) { Bsel = wk; outp = ok; ldbN = HKVc * HDc; nloc = nb - 16; }
    else              { Bsel = wv; outp = ov; ldbN = HKVc * HDc; nloc = nb - 20; }
    int n0 = nloc * 128;
    int m0 = blockIdx.y * 128;
    TF_DECL;
    const float* Aptr = A + (size_t)(m0 + aRow) * Dc + aCol;
    const float* Bptr = Bsel + (size_t)bRow * ldbN + n0 + bCol;

    float4 av0 = *(const float4*)(Aptr);
    float4 av1 = *(const float4*)(Aptr + 4);
    float4 bv0 = *(const float4*)(Bptr);
    float4 bv1 = *(const float4*)(Bptr + 4);
    TF_STORE(0);
    __syncthreads();

    int nTiles = Dc >> 4;
    for (int t = 0; t < nTiles; t++) {
        int cur = t & 1, nxt = cur ^ 1;
        if (t + 1 < nTiles) {
            int k0 = (t + 1) << 4;
            av0 = *(const float4*)(Aptr + k0);
            av1 = *(const float4*)(Aptr + k0 + 4);
            bv0 = *(const float4*)(Bptr + (size_t)k0 * ldbN);
            bv1 = *(const float4*)(Bptr + (size_t)k0 * ldbN + 4);
        }
        if (cur == 0) { TF_COMPUTE(0); } else { TF_COMPUTE(1); }
        if (t + 1 < nTiles) {
            if (nxt == 0) { TF_STORE(0); } else { TF_STORE(1); }
        }
        __syncthreads();
    }
    #pragma unroll
    for (int mti = 0; mti < 2; mti++)
        #pragma unroll
        for (int nti = 0; nti < 8; nti++) {
            int m = m0 + wm * 32 + mti * 16 + grp;
            int n = n0 + wn * 64 + nti * 8 + tig * 2;
            const float* cc = acc[mti][nti];
            outp[(size_t)m * ldbN + n]           = cc[0];
            outp[(size_t)m * ldbN + n + 1]       = cc[1];
            outp[(size_t)(m + 8) * ldbN + n]     = cc[2];
            outp[(size_t)(m + 8) * ldbN + n + 1] = cc[3];
        }
}

// ---------------- generic tf32 GEMM (R4 double-buffer): C = A@B (+addC) ----------------
__global__ void __launch_bounds__(256) gemm_tf32_kernel(const float* __restrict__ A,
                                                        const float* __restrict__ B,
                                                        float* __restrict__ C,
                                                        const float* __restrict__ addC,
                                                        int K, int lda, int ldbN, int ldc) {
    __shared__ uint32_t As[2][128][20];
    __shared__ uint32_t Bs[2][16][136];
    int m0 = blockIdx.y * 128;
    int n0 = blockIdx.x * 128;
    TF_DECL;
    const float* Aptr = A + (size_t)(m0 + aRow) * lda + aCol;
    const float* Bptr = B + (size_t)bRow * ldbN + n0 + bCol;

    float4 av0 = *(const float4*)(Aptr);
    float4 av1 = *(const float4*)(Aptr + 4);
    float4 bv0 = *(const float4*)(Bptr);
    float4 bv1 = *(const float4*)(Bptr + 4);
    TF_STORE(0);
    __syncthreads();

    int nTiles = K >> 4;
    for (int t = 0; t < nTiles; t++) {
        int cur = t & 1, nxt = cur ^ 1;
        if (t + 1 < nTiles) {
            int k0 = (t + 1) << 4;
            av0 = *(const float4*)(Aptr + k0);
            av1 = *(const float4*)(Aptr + k0 + 4);
            bv0 = *(const float4*)(Bptr + (size_t)k0 * ldbN);
            bv1 = *(const float4*)(Bptr + (size_t)k0 * ldbN + 4);
        }
        if (cur == 0) { TF_COMPUTE(0); } else { TF_COMPUTE(1); }
        if (t + 1 < nTiles) {
            if (nxt == 0) { TF_STORE(0); } else { TF_STORE(1); }
        }
        __syncthreads();
    }
    #pragma unroll
    for (int mti = 0; mti < 2; mti++)
        #pragma unroll
        for (int nti = 0; nti < 8; nti++) {
            int m = m0 + wm * 32 + mti * 16 + grp;
            int n = n0 + wn * 64 + nti * 8 + tig * 2;
            const float* cc = acc[mti][nti];
            float v0 = cc[0], v1 = cc[1], v2 = cc[2], v3 = cc[3];
            if (addC) {
                v0 += addC[(size_t)m * ldc + n];
                v1 += addC[(size_t)m * ldc + n + 1];
                v2 += addC[(size_t)(m + 8) * ldc + n];
                v3 += addC[(size_t)(m + 8) * ldc + n + 1];
            }
            C[(size_t)m * ldc + n]           = v0;
            C[(size_t)m * ldc + n + 1]       = v1;
            C[(size_t)(m + 8) * ldc + n]     = v2;
            C[(size_t)(m + 8) * ldc + n + 1] = v3;
        }
}

// ---------------- QK^T scores (tf32 NT, double-buffered, causal tile skip) ----------------
__global__ void __launch_bounds__(256) qk_tf32_kernel(const float* __restrict__ q,
                                                      const float* __restrict__ k,
                                                      float* __restrict__ scores) {
    __shared__ uint32_t As[2][128][20];
    __shared__ uint32_t Bs2[2][128][20];
    int kb0 = blockIdx.x * 128, q0 = blockIdx.y * 128, z = blockIdx.z;
    if (kb0 > q0) return;
    int b = z / HQc, h = z % HQc, kvh = h / REPc;
    TF_DECL;
    (void)bRow; (void)bCol;
    const float* Aptr = q + ((size_t)(b * Sc + q0 + aRow) * HQc + h) * HDc + aCol;
    const float* Bptr = k + ((size_t)(b * Sc + kb0 + aRow) * HKVc + kvh) * HDc + aCol;

    float4 av0 = *(const float4*)(Aptr);
    float4 av1 = *(const float4*)(Aptr + 4);
    float4 bv0 = *(const float4*)(Bptr);
    float4 bv1 = *(const float4*)(Bptr + 4);
    TF_STORE_NT(0);
    __syncthreads();

    const int nTiles = HDc >> 4;   // 8
    for (int t = 0; t < nTiles; t++) {
        int cur = t & 1, nxt = cur ^ 1;
        if (t + 1 < nTiles) {
            int k0 = (t + 1) << 4;
            av0 = *(const float4*)(Aptr + k0);
            av1 = *(const float4*)(Aptr + k0 + 4);
            bv0 = *(const float4*)(Bptr + k0);
            bv1 = *(const float4*)(Bptr + k0 + 4);
        }
        if (cur == 0) { TF_COMPUTE_NT(0); } else { TF_COMPUTE_NT(1); }
        if (t + 1 < nTiles) {
            if (nxt == 0) { TF_STORE_NT(0); } else { TF_STORE_NT(1); }
        }
        __syncthreads();
    }

    const float scale = 0.08838834764831845f; // 128^-0.5
    #pragma unroll
    for (int mti = 0; mti < 2; mti++)
        #pragma unroll
        for (int nti = 0; nti < 8; nti++) {
            int m = q0 + wm * 32 + mti * 16 + grp;
            int n = kb0 + wn * 64 + nti * 8 + tig * 2;
            const float* cc = acc[mti][nti];
            float* row0 = scores + ((size_t)z * Sc + m) * Sc;
            float* row8 = scores + ((size_t)z * Sc + m + 8) * Sc;
            row0[n]     = cc[0] * scale;
            row0[n + 1] = cc[1] * scale;
            row8[n]     = cc[2] * scale;
            row8[n + 1] = cc[3] * scale;
        }
}

// ---------------- causal softmax: normalize [0..qi], zero-fill only the attnv band ----------------
__global__ void __launch_bounds__(256) softmax_kernel(float* __restrict__ scores) {
    int qi = blockIdx.x, z = blockIdx.y;
    float* row = scores + ((size_t)z * Sc + qi) * Sc;
    int n = qi + 1;
    int tid = threadIdx.x;
    __shared__ float red[256];
    float m = -1e30f;
    for (int i = tid; i < n; i += 256) m = fmaxf(m, row[i]);
    red[tid] = m; __syncthreads();
    for (int st = 128; st > 0; st >>= 1) {
        if (tid < st) red[tid] = fmaxf(red[tid], red[tid + st]);
        __syncthreads();
    }
    float mx = red[0]; __syncthreads();
    float s = 0.f;
    for (int i = tid; i < n; i += 256) s += expf(row[i] - mx);
    red[tid] = s; __syncthreads();
    for (int st = 128; st > 0; st >>= 1) {
        if (tid < st) red[tid] += red[tid + st];
        __syncthreads();
    }
    float inv = 1.f / red[0];
    for (int i = tid; i < n; i += 256) row[i] = expf(row[i] - mx) * inv;
    int bandEnd = (qi & ~127) + 128;   // attnv reads k in [0, bandEnd)
    for (int i = n + tid; i < bandEnd; i += 256) row[i] = 0.f;
}

// ---------------- attn = P @ V (tf32, R4 double-buffer, causal K truncation) ----------------
__global__ void __launch_bounds__(256) attnv_tf32_kernel(const float* __restrict__ P,
                                                         const float* __restrict__ v,
                                                         float* __restrict__ attn) {
    __shared__ uint32_t As[2][128][20];
    __shared__ uint32_t Bs[2][16][136];
    int z = blockIdx.z;
    int b = z / HQc, h = z % HQc, kvh = h / REPc;
    int m0 = blockIdx.y * 128;
    const int ldbN = HKVc * HDc;
    TF_DECL;
    const float* Aptr = P + (size_t)z * Sc * Sc + (size_t)(m0 + aRow) * Sc + aCol;
    const float* Bptr = v + ((size_t)b * Sc * HKVc + kvh) * HDc + (size_t)bRow * ldbN + bCol;

    float4 av0 = *(const float4*)(Aptr);
    float4 av1 = *(const float4*)(Aptr + 4);
    float4 bv0 = *(const float4*)(Bptr);
    float4 bv1 = *(const float4*)(Bptr + 4);
    TF_STORE(0);
    __syncthreads();

    int nTiles = (m0 + 128) >> 4;   // rows beyond qi within the band hold zeroed probs
    for (int t = 0; t < nTiles; t++) {
        int cur = t & 1, nxt = cur ^ 1;
        if (t + 1 < nTiles) {
            int k0 = (t + 1) << 4;
            av0 = *(const float4*)(Aptr + k0);
            av1 = *(const float4*)(Aptr + k0 + 4);
            bv0 = *(const float4*)(Bptr + (size_t)k0 * ldbN);
            bv1 = *(const float4*)(Bptr + (size_t)k0 * ldbN + 4);
        }
        if (cur == 0) { TF_COMPUTE(0); } else { TF_COMPUTE(1); }
        if (t + 1 < nTiles) {
            if (nxt == 0) { TF_STORE(0); } else { TF_STORE(1); }
        }
        __syncthreads();
    }
    #pragma unroll
    for (int mti = 0; mti < 2; mti++)
        #pragma unroll
        for (int nti = 0; nti < 8; nti++) {
            int m = m0 + wm * 32 + mti * 16 + grp;
            int n = wn * 64 + nti * 8 + tig * 2;
            const float* cc = acc[mti][nti];
            attn[((size_t)(b * Sc + m) * HQc + h) * HDc + n]         = cc[0];
            attn[((size_t)(b * Sc + m) * HQc + h) * HDc + n + 1]     = cc[1];
            attn[((size_t)(b * Sc + m + 8) * HQc + h) * HDc + n]     = cc[2];
            attn[((size_t)(b * Sc + m + 8) * HQc + h) * HDc + n + 1] = cc[3];
        }
}

// ---------------- elementwise silu(a)*b -> a ----------------
__global__ void __launch_bounds__(256) silumul_kernel(float* __restrict__ a,
                                                      const float* __restrict__ b,
                                                      int n) {
    int i = blockIdx.x * 256 + threadIdx.x;
    if (i < n) {
        float v = a[i];
        a[i] = v / (1.f + expf(-v)) * b[i];
    }
}

// ---------------- router: logits, sigmoid, top-4, renorm ----------------
__global__ void __launch_bounds__(256) router_kernel(const float* __restrict__ x,
                                                     const float* __restrict__ gate_w) {
    int t = blockIdx.x;
    int tid = threadIdx.x;
    int lane = tid & 31, w = tid >> 5;
    const float* xr = x + (size_t)t * Dc;
    float acc[4] = {0.f, 0.f, 0.f, 0.f};
    for (int d = lane; d < Dc; d += 32) {
        float xv = xr[d];
        #pragma unroll
        for (int j = 0; j < 4; j++)
            acc[j] = fmaf(xv, gate_w[(size_t)d * Ec + w * 4 + j], acc[j]);
    }
    #pragma unroll
    for (int j = 0; j < 4; j++)
        for (int o = 16; o > 0; o >>= 1)
            acc[j] += __shfl_down_sync(0xffffffffu, acc[j], o);
    __shared__ float lg[Ec];
    if (lane == 0) {
        #pragma unroll
        for (int j = 0; j < 4; j++) lg[w * 4 + j] = acc[j];
    }
    __syncthreads();
    if (tid == 0) {
        float gg[Ec];
        #pragma unroll
        for (int e = 0; e < Ec; e++) gg[e] = 1.f / (1.f + expf(-lg[e]));
        float tv[TOPK]; int ti[TOPK]; float sum = 0.f;
        for (int j = 0; j < TOPK; j++) {
            int best = 0; float bv = -1e30f;
            for (int e = 0; e < Ec; e++)
                if (gg[e] > bv) { bv = gg[e]; best = e; }
            gg[best] = -1e30f;
            tv[j] = bv; ti[j] = best; sum += bv;
        }
        float inv = 1.f / sum;
        for (int j = 0; j < TOPK; j++) {
            g_topi[t * TOPK + j] = ti[j];
            g_topw[t * TOPK + j] = tv[j] * inv;
        }
    }
}

// ---------------- expert grouping ----------------
__global__ void __launch_bounds__(256) count_scan_kernel() {
    __shared__ int sc[Ec];
    int tid = threadIdx.x;
    if (tid < Ec) sc[tid] = 0;
    __syncthreads();
    for (int i = tid; i < Tc * TOPK; i += 256) atomicAdd(&sc[g_topi[i]], 1);
    __syncthreads();
    if (tid == 0) {
        int run = 0;
        for (int e = 0; e < Ec; e++) {
            g_offsets[e] = run; g_cursor[e] = run; g_counts[e] = sc[e];
            run += sc[e];
        }
    }
}

__global__ void __launch_bounds__(256) scatter_kernel() {
    int i = blockIdx.x * 256 + threadIdx.x;
    if (i < Tc * TOPK) {
        int t = i >> 2;
        int e = g_topi[i];
        int p = atomicAdd(&g_cursor[e], 1);
        g_slot_tok[p] = t;
        g_slot_w[p] = g_topw[i];
    }
}

// ---------------- routed expert up/gate GEMM (tf32, R4 double-buffer, gathered A) ----------------
__global__ void __launch_bounds__(256) moe_up_tf32_kernel(const float* __restrict__ X,
                                                          const float* __restrict__ W,
                                                          float* __restrict__ Cb,
                                                          int Nn, int Kd) {
    __shared__ uint32_t As[2][128][20];
    __shared__ uint32_t Bs[2][16][136];
    int e = blockIdx.z;
    int cnt = g_counts[e];
    int m0 = blockIdx.y * 128;
    if (m0 >= cnt) return;
    int off = g_offsets[e];
    int n0 = blockIdx.x * 128;
    TF_DECL;
    int gRow = m0 + aRow;
    int srow = (gRow < cnt) ? g_slot_tok[off + gRow] : g_slot_tok[off];
    const float* Aptr = X + (size_t)srow * Kd + aCol;
    const float* Bptr = W + (size_t)e * Kd * Nn + (size_t)bRow * Nn + n0 + bCol;

    float4 av0 = *(const float4*)(Aptr);
    float4 av1 = *(const float4*)(Aptr + 4);
    float4 bv0 = *(const float4*)(Bptr);
    float4 bv1 = *(const float4*)(Bptr + 4);
    TF_STORE(0);
    __syncthreads();

    int nTiles = Kd >> 4;
    for (int t = 0; t < nTiles; t++) {
        int cur = t & 1, nxt = cur ^ 1;
        if (t + 1 < nTiles) {
            int k0 = (t + 1) << 4;
            av0 = *(const float4*)(Aptr + k0);
            av1 = *(const float4*)(Aptr + k0 + 4);
            bv0 = *(const float4*)(Bptr + (size_t)k0 * Nn);
            bv1 = *(const float4*)(Bptr + (size_t)k0 * Nn + 4);
        }
        if (cur == 0) { TF_COMPUTE(0); } else { TF_COMPUTE(1); }
        if (t + 1 < nTiles) {
            if (nxt == 0) { TF_STORE(0); } else { TF_STORE(1); }
        }
        __syncthreads();
    }
    #pragma unroll
    for (int mti = 0; mti < 2; mti++)
        #pragma unroll
        for (int nti = 0; nti < 8; nti++) {
            int r = m0 + wm * 32 + mti * 16 + grp;
            int n = n0 + wn * 64 + nti * 8 + tig * 2;
            const float* cc = acc[mti][nti];
            if (r < cnt) {
                Cb[(size_t)(off + r) * Nn + n]     = cc[0];
                Cb[(size_t)(off + r) * Nn + n + 1] = cc[1];
            }
            if (r + 8 < cnt) {
                Cb[(size_t)(off + r + 8) * Nn + n]     = cc[2];
                Cb[(size_t)(off + r + 8) * Nn + n + 1] = cc[3];
            }
        }
}

// ---------------- routed expert down GEMM (tf32, R4 double-buffer): atomicAdd into out ----------------
__global__ void __launch_bounds__(256) moe_down_tf32_kernel(const float* __restrict__ Ibuf,
                                                            const float* __restrict__ Wd,
                                                            float* __restrict__ out,
                                                            int Nn, int Kd) {
    __shared__ uint32_t As[2][128][20];
    __shared__ uint32_t Bs[2][16][136];
    int e = blockIdx.z;
    int cnt = g_counts[e];
    int m0 = blockIdx.y * 128;
    if (m0 >= cnt) return;
    int off = g_offsets[e];
    int n0 = blockIdx.x * 128;
    TF_DECL;
    int gRow = m0 + aRow;
    int arow = off + ((gRow < cnt) ? gRow : 0);
    const float* Aptr = Ibuf + (size_t)arow * Kd + aCol;
    const float* Bptr = Wd + (size_t)e * Kd * Nn + (size_t)bRow * Nn + n0 + bCol;

    float4 av0 = *(const float4*)(Aptr);
    float4 av1 = *(const float4*)(Aptr + 4);
    float4 bv0 = *(const float4*)(Bptr);
    float4 bv1 = *(const float4*)(Bptr + 4);
    TF_STORE(0);
    __syncthreads();

    int nTiles = Kd >> 4;
    for (int t = 0; t < nTiles; t++) {
        int cur = t & 1, nxt = cur ^ 1;
        if (t + 1 < nTiles) {
            int k0 = (t + 1) << 4;
            av0 = *(const float4*)(Aptr + k0);
            av1 = *(const float4*)(Aptr + k0 + 4);
            bv0 = *(const float4*)(Bptr + (size_t)k0 * Nn);
            bv1 = *(const float4*)(Bptr + (size_t)k0 * Nn + 4);
        }
        if (cur == 0) { TF_COMPUTE(0); } else { TF_COMPUTE(1); }
        if (t + 1 < nTiles) {
            if (nxt == 0) { TF_STORE(0); } else { TF_STORE(1); }
        }
        __syncthreads();
    }
    #pragma unroll
    for (int mti = 0; mti < 2; mti++)
        #pragma unroll
        for (int nti = 0; nti < 8; nti++) {
            int r = m0 + wm * 32 + mti * 16 + grp;
            int n = n0 + wn * 64 + nti * 8 + tig * 2;
            const float* cc = acc[mti][nti];
            if (r < cnt) {
                int slot = off + r;
                float wgt = g_slot_w[slot];
                int tok = g_slot_tok[slot];
                atomicAdd(&out[(size_t)tok * Nn + n],     wgt * cc[0]);
                atomicAdd(&out[(size_t)tok * Nn + n + 1], wgt * cc[1]);
            }
            if (r + 8 < cnt) {
                int slot = off + r + 8;
                float wgt = g_slot_w[slot];
                int tok = g_slot_tok[slot];
                atomicAdd(&out[(size_t)tok * Nn + n],     wgt * cc[2]);
                atomicAdd(&out[(size_t)tok * Nn + n + 1], wgt * cc[3]);
            }
        }
}

// ---------------- host launch ----------------
extern "C" void kernel_launch(void* const* d_in, const int* in_sizes, int n_in,
                              void* d_out, int out_size) {
    const int*   positions = (const int*)d_in[0];
    const float* hidden    = (const float*)d_in[1];
    const float* in_ln     = (const float*)d_in[2];
    const float* post_ln   = (const float*)d_in[3];
    const float* q_norm    = (const float*)d_in[4];
    const float* k_norm    = (const float*)d_in[5];
    const float* wq        = (const float*)d_in[6];
    const float* wk        = (const float*)d_in[7];
    const float* wv        = (const float*)d_in[8];
    const float* wo        = (const float*)d_in[9];
    const float* gate_w    = (const float*)d_in[10];
    const float* sh_wg     = (const float*)d_in[11];
    const float* sh_wu     = (const float*)d_in[12];
    const float* sh_wd     = (const float*)d_in[13];
    const float* e_wg      = (const float*)d_in[14];
    const float* e_wu      = (const float*)d_in[15];
    const float* e_wd      = (const float*)d_in[16];
    float* out = (float*)d_out;

    float *p_h, *p_q, *p_k, *p_v, *p_scores, *p_attn, *p_h2, *p_x, *p_g1, *p_u1,
          *p_eg, *p_eu;
    cudaGetSymbolAddress((void**)&p_h, g_h);
    cudaGetSymbolAddress((void**)&p_q, g_q);
    cudaGetSymbolAddress((void**)&p_k, g_k);
    cudaGetSymbolAddress((void**)&p_v, g_v);
    cudaGetSymbolAddress((void**)&p_scores, g_scores);
    cudaGetSymbolAddress((void**)&p_attn, g_attn);
    cudaGetSymbolAddress((void**)&p_h2, g_h2);
    cudaGetSymbolAddress((void**)&p_x, g_x);
    cudaGetSymbolAddress((void**)&p_g1, g_g1);
    cudaGetSymbolAddress((void**)&p_u1, g_u1);
    cudaGetSymbolAddress((void**)&p_eg, g_eg);
    cudaGetSymbolAddress((void**)&p_eu, g_eu);

    // 1. input RMSNorm
    rmsnorm_kernel<<<Tc, 256>>>(hidden, in_ln, p_h);

    // 2. fused QKV projection
    qkv_tf32_kernel<<<dim3(24, Tc / 128), 256>>>(p_h, wq, wk, wv, p_q, p_k, p_v);

    // 3. qk-norm + RoPE
    qknorm_rope_kernel<<<dim3(Tc, HQc), 128>>>(p_q, q_norm, positions, HQc);
    qknorm_rope_kernel<<<dim3(Tc, HKVc), 128>>>(p_k, k_norm, positions, HKVc);

    // 4. scores (tf32 NT, causal tile skip)
    qk_tf32_kernel<<<dim3(Sc / 128, Sc / 128, Bc * HQc), 256>>>(p_q, p_k, p_scores);

    // 5. causal softmax (bounded zero-fill)
    softmax_kernel<<<dim3(Sc, Bc * HQc), 256>>>(p_scores);

    // 6. attn = P @ V
    attnv_tf32_kernel<<<dim3(1, Sc / 128, Bc * HQc), 256>>>(p_scores, p_v, p_attn);

    // 7. output proj + residual
    gemm_tf32_kernel<<<dim3(Dc / 128, Tc / 128), 256>>>(p_attn, wo, p_h2, hidden,
        HQc * HDc, HQc * HDc, Dc, Dc);

    // 8. post-attn RMSNorm
    rmsnorm_kernel<<<Tc, 256>>>(p_h2, post_ln, p_x);

    // 9. shared expert SwiGLU; down-proj fused with resid2 directly into out
    gemm_tf32_kernel<<<dim3(FSc / 128, Tc / 128), 256>>>(p_x, sh_wg, p_g1, nullptr,
        Dc, Dc, FSc, FSc);
    gemm_tf32_kernel<<<dim3(FSc / 128, Tc / 128), 256>>>(p_x, sh_wu, p_u1, nullptr,
        Dc, Dc, FSc, FSc);
    silumul_kernel<<<(Tc * FSc + 255) / 256, 256>>>(p_g1, p_u1, Tc * FSc);
    // out = shared + resid2; moe atomics add on top afterwards
    gemm_tf32_kernel<<<dim3(Dc / 128, Tc / 128), 256>>>(p_g1, sh_wd, out, p_h2,
        FSc, FSc, Dc, Dc);

    // 10. routing + grouping
    router_kernel<<<Tc, 256>>>(p_x, gate_w);
    count_scan_kernel<<<1, 256>>>();
    scatter_kernel<<<(Tc * TOPK + 255) / 256, 256>>>();

    // 11. routed experts: gate/up (gathered), silu-mul
    moe_up_tf32_kernel<<<dim3(Fc / 128, (Tc * TOPK) / 128, Ec), 256>>>(p_x, e_wg, p_eg, Fc, Dc);
    moe_up_tf32_kernel<<<dim3(Fc / 128, (Tc * TOPK) / 128, Ec), 256>>>(p_x, e_wu, p_eu, Fc, Dc);
    silumul_kernel<<<(Tc * TOPK * Fc + 255) / 256, 256>>>(p_eg, p_eu, Tc * TOPK * Fc);

    // 12. routed down-proj, weighted atomic accumulate into out
    moe_down_tf32_kernel<<<dim3(Dc / 128, (Tc * TOPK) / 128, Ec), 256>>>(p_eg, e_wd, out, Dc, Fc);
}